// round 1
// baseline (speedup 1.0000x reference)
#include <cuda_runtime.h>

#define NXg 1024
#define NYg 85
#define N_AMPS 1500

__global__ __launch_bounds__(256)
void echellogram_kernel(
    const int*   __restrict__ index_p,     // d_in[0]
    const float* __restrict__ bkg_p,       // d_in[1]
    const float* __restrict__ s_coeffs,    // d_in[2] (3)
    const float* __restrict__ amps,        // d_in[3] (1500)
    const float* __restrict__ smooth_p,    // d_in[4]
    const float* __restrict__ lam_coeffs,  // d_in[5] (4)
    const float* __restrict__ p_coeffs,    // d_in[6] (2x2)
    const float* __restrict__ src_amps,    // d_in[7] (1500)
    const float* __restrict__ fiducial,    // d_in[8] (2)
    const float* __restrict__ lam_vector,  // d_in[9] (1500)
    float*       __restrict__ out)
{
    const float SIGMA        = 0.42f;
    const float INV_SIGMA    = 1.0f / 0.42f;
    const float SLIT         = 12.0f;
    const float INV_SQRT_2PI = 0.3989422804014327f;
    const float LOG_SQRT_2PI = 0.9189385332046727f;

    int i = blockIdx.x * blockDim.x + threadIdx.x;
    if (i >= NXg * NYg) return;
    int x = i / NYg;
    int y = i - x * NYg;
    float xf = (float)x;
    float yf = (float)y;

    // --- scalar params (broadcast L1 loads) ---
    int   idx        = index_p[0];
    float bkg        = bkg_p[0];
    float smoothness = smooth_p[0];
    float s0 = s_coeffs[0], s1 = s_coeffs[1], s2 = s_coeffs[2];
    float c0 = lam_coeffs[0], c1 = lam_coeffs[1], c2 = lam_coeffs[2], c3 = lam_coeffs[3];
    float f0 = fiducial[0],   f1 = fiducial[1];
    float pc0 = p_coeffs[2 * idx + 0];
    float pc1 = p_coeffs[2 * idx + 1];

    // --- along-slit coordinate & wavelength surface (match ref op order) ---
    float ss = s1 * (yf - s0 - s2 * xf);

    float xn = (xf - 512.0f) / 512.0f;
    float yn = (yf - 42.5f) / 42.5f;
    float cx1 = f1 * (1.0f + c1 * 0.01f) * 512.0f;
    float cx2 = 1.0f + c2;
    float lam = f0 + c0 + cx1 * xn + cx2 * (2.0f * xn * xn - 1.0f) + c3 * yn;

    // --- soft slit mask ---
    float inv_beta = __expf(-smoothness);
    float e1 = 1.0f / (1.0f + __expf(-(ss * inv_beta)));
    float e2 = 1.0f / (1.0f + __expf(-((SLIT - ss) * inv_beta)));
    float emask = e1 * e2;

    // --- windowed Gaussian-comb reduction over amps axis ---
    float lam0 = lam_vector[0];
    float lamN = lam_vector[N_AMPS - 1];
    float dlam = (lamN - lam0) * (1.0f / (float)(N_AMPS - 1));

    int lo = 0, hi = N_AMPS - 1;
    if (fabsf(dlam) > 1e-20f) {
        float inv_dlam = 1.0f / dlam;
        float t  = (lam - lam0) * inv_dlam;          // fractional center index
        float hw = 6.0f * SIGMA * fabsf(inv_dlam);   // 6-sigma half-window (~12 idx)
        lo = max(0,          (int)floorf(t - hw));
        hi = min(N_AMPS - 1, (int)ceilf (t + hw));
    }

    float sky = 0.0f, src = 0.0f;
    #pragma unroll 4
    for (int a = lo; a <= hi; ++a) {
        float z = (lam - lam_vector[a]) * INV_SIGMA;
        float p = __expf(-0.5f * z * z);
        sky = fmaf(amps[a],     p, sky);
        src = fmaf(src_amps[a], p, src);
    }
    float norm = INV_SQRT_2PI * INV_SIGMA;
    sky *= norm;
    src *= norm;

    // --- source spatial profile ---
    float sig_s = __expf(pc1);
    float u = (ss - pc0) / sig_s;
    float src_prof = __expf(fmaf(-0.5f * u, u, -pc1 - LOG_SQRT_2PI));

    out[i] = emask * sky + src_prof * src + bkg;
}

extern "C" void kernel_launch(void* const* d_in, const int* in_sizes, int n_in,
                              void* d_out, int out_size) {
    (void)in_sizes; (void)n_in; (void)out_size;
    const int*   index_p    = (const int*)  d_in[0];
    const float* bkg_p      = (const float*)d_in[1];
    const float* s_coeffs   = (const float*)d_in[2];
    const float* amps       = (const float*)d_in[3];
    const float* smooth_p   = (const float*)d_in[4];
    const float* lam_coeffs = (const float*)d_in[5];
    const float* p_coeffs   = (const float*)d_in[6];
    const float* src_amps   = (const float*)d_in[7];
    const float* fiducial   = (const float*)d_in[8];
    const float* lam_vector = (const float*)d_in[9];
    float* out = (float*)d_out;

    const int total = NXg * NYg;           // 87040
    const int threads = 256;
    const int blocks = (total + threads - 1) / threads;  // 340
    echellogram_kernel<<<blocks, threads>>>(
        index_p, bkg_p, s_coeffs, amps, smooth_p, lam_coeffs,
        p_coeffs, src_amps, fiducial, lam_vector, out);
}